// round 5
// baseline (speedup 1.0000x reference)
#include <cuda_runtime.h>
#include <math.h>

#define BB 16
#define CC 3
#define HH 512
#define WW 512
#define HWv (HH*WW)

#define TX 32
#define TY 16
#define TILESX (WW/TX)   // 16
#define TILESY (HH/TY)   // 32
#define NTHREADS (TX*TY) // 512

__device__ double g_acc;
__device__ double g_sum_ir[BB];

// ---------------------------------------------------------------------------
// 0) zero accumulators
// ---------------------------------------------------------------------------
__global__ void init_kernel() {
    int t = threadIdx.x;
    if (t == 0) g_acc = 0.0;
    if (t < BB) g_sum_ir[t] = 0.0;
}

// ---------------------------------------------------------------------------
// 1) per-batch gray mean of input_ir (numerator; divided later)
//    gray = 0.2989*R + 0.587*G + 0.114*B  (note: contrast uses 0.2989, not .299)
// ---------------------------------------------------------------------------
#define IRBLOCKS_PER_BATCH 64
__global__ void ir_mean_kernel(const float* __restrict__ ir) {
    int b   = blockIdx.x / IRBLOCKS_PER_BATCH;
    int blk = blockIdx.x % IRBLOCKS_PER_BATCH;
    const int pix_per_block = HWv / IRBLOCKS_PER_BATCH; // 4096
    int base = blk * pix_per_block;

    const float* r  = ir + (size_t)b * CC * HWv;
    const float* g  = r + HWv;
    const float* bl = g + HWv;

    float s = 0.f;
    for (int i = threadIdx.x; i < pix_per_block; i += blockDim.x) {
        int p = base + i;
        s += 0.2989f * r[p] + 0.587f * g[p] + 0.114f * bl[p];
    }
    #pragma unroll
    for (int o = 16; o; o >>= 1) s += __shfl_down_sync(0xffffffffu, s, o);

    __shared__ float ws[8];
    int wid = threadIdx.x >> 5, lid = threadIdx.x & 31;
    if (lid == 0) ws[wid] = s;
    __syncthreads();
    if (wid == 0) {
        s = (lid < (int)(blockDim.x >> 5)) ? ws[lid] : 0.f;
        #pragma unroll
        for (int o = 4; o; o >>= 1) s += __shfl_down_sync(0xffffffffu, s, o);
        if (lid == 0) atomicAdd(&g_sum_ir[b], (double)s);
    }
}

// ---------------------------------------------------------------------------
// 2) fused main pass: build Fuse / R_vis / R_ir tiles (+1 halo, zero-padded),
//    Sobel gx/gy, joint maxima, chroma diff, weighted L1 accumulation.
// ---------------------------------------------------------------------------
__global__ __launch_bounds__(NTHREADS)
void fusion_main_kernel(const float* __restrict__ vis,
                        const float* __restrict__ ir,
                        const float* __restrict__ outp,
                        const float* __restrict__ mask) {
    __shared__ float sF[CC][TY+2][TX+2];
    __shared__ float sV[CC][TY+2][TX+2];
    __shared__ float sI[CC][TY+2][TX+2];

    int tile = blockIdx.x;
    int b  = tile / (TILESX * TILESY);
    int t2 = tile % (TILESX * TILESY);
    int ty = t2 / TILESX;
    int tx = t2 % TILESX;
    int h0 = ty * TY, w0 = tx * TX;

    float meanb = (float)(g_sum_ir[b] * (1.0 / (double)HWv));

    size_t bbase = (size_t)b * CC * HWv;
    int tid = threadIdx.x;

    const int HALO = (TY + 2) * (TX + 2); // 612
    for (int idx = tid; idx < CC * HALO; idx += NTHREADS) {
        int c  = idx / HALO;
        int r  = idx % HALO;
        int hy = r / (TX + 2);
        int hx = r % (TX + 2);
        int h = h0 + hy - 1, w = w0 + hx - 1;
        float f = 0.f, v = 0.f, iq = 0.f;
        if ((unsigned)h < HH && (unsigned)w < WW) {   // SAME -> zero pad outside
            size_t p = bbase + (size_t)c * HWv + (size_t)h * WW + (size_t)w;
            f = outp[p] * mask[p];
            float vv = sqrtf(vis[p]);                 // gamma 0.5, gain 1
            v = fminf(fmaxf(vv, 0.f), 1.f);
            float ii = 1.8f * ir[p] - 0.8f * meanb;   // contrast 1.8
            iq = fminf(fmaxf(ii, 0.f), 1.f);
        }
        sF[c][hy][hx] = f;
        sV[c][hy][hx] = v;
        sI[c][hy][hx] = iq;
    }
    __syncthreads();

    int lx = tid % TX, ly = tid / TX;
    int y = ly + 1, x = lx + 1;

    float con = 0.f, gsum = 0.f;
    float Fc[3], Vc[3];

    #pragma unroll
    for (int c = 0; c < CC; c++) {
        float F = sF[c][y][x];
        float V = sV[c][y][x];
        float I = sI[c][y][x];
        Fc[c] = F; Vc[c] = V;

        con += fabsf(F - fmaxf(V, I));

        // Sobel X (cross-correlation): [-1 0 1; -2 0 2; -1 0 1]
        float fgx = (sF[c][y-1][x+1] - sF[c][y-1][x-1])
                  + 2.f*(sF[c][y][x+1] - sF[c][y][x-1])
                  + (sF[c][y+1][x+1] - sF[c][y+1][x-1]);
        float vgx = (sV[c][y-1][x+1] - sV[c][y-1][x-1])
                  + 2.f*(sV[c][y][x+1] - sV[c][y][x-1])
                  + (sV[c][y+1][x+1] - sV[c][y+1][x-1]);
        float igx = (sI[c][y-1][x+1] - sI[c][y-1][x-1])
                  + 2.f*(sI[c][y][x+1] - sI[c][y][x-1])
                  + (sI[c][y+1][x+1] - sI[c][y+1][x-1]);

        // Sobel Y (cross-correlation): [1 2 1; 0 0 0; -1 -2 -1]
        float fgy = (sF[c][y-1][x-1] + 2.f*sF[c][y-1][x] + sF[c][y-1][x+1])
                  - (sF[c][y+1][x-1] + 2.f*sF[c][y+1][x] + sF[c][y+1][x+1]);
        float vgy = (sV[c][y-1][x-1] + 2.f*sV[c][y-1][x] + sV[c][y-1][x+1])
                  - (sV[c][y+1][x-1] + 2.f*sV[c][y+1][x] + sV[c][y+1][x+1]);
        float igy = (sI[c][y-1][x-1] + 2.f*sI[c][y-1][x] + sI[c][y-1][x+1])
                  - (sI[c][y+1][x-1] + 2.f*sI[c][y+1][x] + sI[c][y+1][x+1]);

        gsum += fabsf(fgx - fmaxf(vgx, igx));
        gsum += fabsf(fgy - fmaxf(vgy, igy));
    }

    // Chroma: +0.5 cancels in the differences.
    float YF  = 0.299f*Fc[0] + 0.587f*Fc[1] + 0.114f*Fc[2];
    float CrF = (Fc[0] - YF) * 0.713f;
    float CbF = (Fc[2] - YF) * 0.564f;
    float YV  = 0.299f*Vc[0] + 0.587f*Vc[1] + 0.114f*Vc[2];
    float CrV = (Vc[0] - YV) * 0.713f;
    float CbV = (Vc[2] - YV) * 0.564f;
    float color = fabsf(CbF - CbV) + fabsf(CrF - CrV);

    const float inv3 = 1.0f / (float)(BB * CC * HWv); // 1/12582912
    const float inv1 = 1.0f / (float)(BB * HWv);      // 1/4194304
    // loss = 0.5*con/N3 + 0.2*(0.5*gx + 0.5*gy)/N3 + color/N1
    float acc = inv3 * (0.5f * con + 0.1f * gsum) + inv1 * color;

    // block reduction
    #pragma unroll
    for (int o = 16; o; o >>= 1) acc += __shfl_down_sync(0xffffffffu, acc, o);
    __shared__ float ws[NTHREADS / 32];
    int wid = tid >> 5, lid = tid & 31;
    if (lid == 0) ws[wid] = acc;
    __syncthreads();
    if (wid == 0) {
        acc = (lid < NTHREADS / 32) ? ws[lid] : 0.f;
        #pragma unroll
        for (int o = 8; o; o >>= 1) acc += __shfl_down_sync(0xffffffffu, acc, o);
        if (lid == 0) atomicAdd(&g_acc, (double)acc);
    }
}

// ---------------------------------------------------------------------------
// 3) finalize
// ---------------------------------------------------------------------------
__global__ void finalize_kernel(float* __restrict__ out) {
    out[0] = (float)g_acc;
}

extern "C" void kernel_launch(void* const* d_in, const int* in_sizes, int n_in,
                              void* d_out, int out_size) {
    const float* vis  = (const float*)d_in[0];
    const float* ir   = (const float*)d_in[1];
    const float* outp = (const float*)d_in[2];
    const float* mask = (const float*)d_in[3];
    float* out = (float*)d_out;

    init_kernel<<<1, 32>>>();
    ir_mean_kernel<<<BB * IRBLOCKS_PER_BATCH, 256>>>(ir);
    fusion_main_kernel<<<BB * TILESX * TILESY, NTHREADS>>>(vis, ir, outp, mask);
    finalize_kernel<<<1, 1>>>(out);
}